// round 1
// baseline (speedup 1.0000x reference)
#include <cuda_runtime.h>
#include <cuda_bf16.h>
#include <mma.h>

using namespace nvcuda;

#define BN     200704   // 4096 * 49 rows
#define CDIM   128
#define HEADS  4
#define HD     32
#define NTOK   49
#define NPAD   64
#define NWIN   64

// ---------------- scratch (device globals: allocation-free) ----------------
__device__ float g_q[BN * CDIM];
__device__ float g_k[BN * CDIM];
__device__ float g_v[BN * CDIM];
__device__ float g_ctx[BN * CDIM];

// ============================================================================
// Projection GEMM: Y[M,128] = X[M,128] @ W^T + b        (W stored [out,in])
// grid.x = M/128, 256 threads, tf32 wmma, full K in smem.
// ============================================================================
__global__ void proj_kernel(const float* __restrict__ X,
                            const float* __restrict__ W,
                            const float* __restrict__ bias,
                            float* __restrict__ Y) {
    constexpr int LD = 132;
    extern __shared__ float sm[];
    float* sA = sm;              // 128 x LD  (X tile)
    float* sB = sm + 128 * LD;   // 128 x LD  (W, row-major [j][c])

    const int tid = threadIdx.x;
    const long rowBase = (long)blockIdx.x * 128;

    for (int idx = tid; idx < 128 * 128; idx += 256) {
        int r = idx >> 7, c = idx & 127;
        sA[r * LD + c] = X[(rowBase + r) * CDIM + c];
        sB[r * LD + c] = W[idx];
    }
    __syncthreads();

    const int warp = tid >> 5;
    const int wm = (warp >> 1) * 32;   // 0,32,64,96
    const int wn = (warp & 1) * 64;    // 0,64

    wmma::fragment<wmma::accumulator, 16, 16, 8, float> acc[2][4];
    #pragma unroll
    for (int mi = 0; mi < 2; mi++)
        #pragma unroll
        for (int ni = 0; ni < 4; ni++) wmma::fill_fragment(acc[mi][ni], 0.f);

    #pragma unroll 4
    for (int kk = 0; kk < 128; kk += 8) {
        wmma::fragment<wmma::matrix_a, 16, 16, 8, wmma::precision::tf32, wmma::row_major> a[2];
        wmma::fragment<wmma::matrix_b, 16, 16, 8, wmma::precision::tf32, wmma::col_major> b[4];
        #pragma unroll
        for (int mi = 0; mi < 2; mi++) {
            wmma::load_matrix_sync(a[mi], sA + (wm + mi * 16) * LD + kk, LD);
            #pragma unroll
            for (int t = 0; t < a[mi].num_elements; t++)
                a[mi].x[t] = wmma::__float_to_tf32(a[mi].x[t]);
        }
        #pragma unroll
        for (int ni = 0; ni < 4; ni++) {
            // B(k=c, n=j) at sB[j*LD + c]  == W[j][c]  (col_major view)
            wmma::load_matrix_sync(b[ni], sB + (wn + ni * 16) * LD + kk, LD);
            #pragma unroll
            for (int t = 0; t < b[ni].num_elements; t++)
                b[ni].x[t] = wmma::__float_to_tf32(b[ni].x[t]);
            #pragma unroll
            for (int mi = 0; mi < 2; mi++)
                wmma::mma_sync(acc[mi][ni], a[mi], b[ni], acc[mi][ni]);
        }
    }
    __syncthreads();   // A tile no longer needed; reuse as output staging

    #pragma unroll
    for (int mi = 0; mi < 2; mi++)
        #pragma unroll
        for (int ni = 0; ni < 4; ni++)
            wmma::store_matrix_sync(sA + (wm + mi * 16) * LD + wn + ni * 16,
                                    acc[mi][ni], LD, wmma::mem_row_major);
    __syncthreads();

    for (int idx = tid; idx < 128 * 128; idx += 256) {
        int r = idx >> 7, c = idx & 127;
        Y[(rowBase + r) * CDIM + c] = sA[r * LD + c] + bias[c];
    }
}

// ============================================================================
// Per-window attention: S = scale*QK^T + bias + mask ; softmax ; ctx = S @ V
// grid.x = 4096 (one CTA per window), 256 threads (2 warps per head).
// ============================================================================
__global__ void attn_kernel(const float* __restrict__ mask,
                            const float* __restrict__ rpb,
                            const int*   __restrict__ relidx) {
    constexpr int LD = 132;  // Q/K/V/ctx row stride (floats)
    constexpr int LS = 68;   // S row stride (floats)
    extern __shared__ float sm[];
    float* sQ = sm;
    float* sK = sQ + NPAD * LD;
    float* sV = sK + NPAD * LD;
    float* sS = sV + NPAD * LD;                // HEADS * 64 * LS
    float* sO = sS + HEADS * NPAD * LS;        // 64 x LD

    const int tid = threadIdx.x;
    const int w = blockIdx.x;
    const long base = (long)w * NTOK * CDIM;

    // load window Q/K/V, zero-pad rows 49..63
    for (int idx = tid; idx < NPAD * CDIM; idx += 256) {
        int r = idx >> 7, c = idx & 127;
        float q = 0.f, k = 0.f, v = 0.f;
        if (r < NTOK) {
            long g = base + r * CDIM + c;
            q = g_q[g]; k = g_k[g]; v = g_v[g];
        }
        sQ[r * LD + c] = q;
        sK[r * LD + c] = k;
        sV[r * LD + c] = v;
    }
    __syncthreads();

    const int warp = tid >> 5;
    const int h  = warp >> 1;          // head 0..3
    const int mo = (warp & 1) * 32;    // m offset within 64

    // -------- S = Q @ K^T (per head, 64x64, k=32) --------
    {
        wmma::fragment<wmma::accumulator, 16, 16, 8, float> acc[2][4];
        #pragma unroll
        for (int mi = 0; mi < 2; mi++)
            #pragma unroll
            for (int ni = 0; ni < 4; ni++) wmma::fill_fragment(acc[mi][ni], 0.f);

        #pragma unroll
        for (int kk = 0; kk < HD; kk += 8) {
            wmma::fragment<wmma::matrix_a, 16, 16, 8, wmma::precision::tf32, wmma::row_major> a[2];
            wmma::fragment<wmma::matrix_b, 16, 16, 8, wmma::precision::tf32, wmma::col_major> b[4];
            #pragma unroll
            for (int mi = 0; mi < 2; mi++) {
                wmma::load_matrix_sync(a[mi], sQ + (mo + mi * 16) * LD + h * HD + kk, LD);
                #pragma unroll
                for (int t = 0; t < a[mi].num_elements; t++)
                    a[mi].x[t] = wmma::__float_to_tf32(a[mi].x[t]);
            }
            #pragma unroll
            for (int ni = 0; ni < 4; ni++) {
                // B(k=d, n=j) at sK[j*LD + h*HD + kk + d]
                wmma::load_matrix_sync(b[ni], sK + (ni * 16) * LD + h * HD + kk, LD);
                #pragma unroll
                for (int t = 0; t < b[ni].num_elements; t++)
                    b[ni].x[t] = wmma::__float_to_tf32(b[ni].x[t]);
                #pragma unroll
                for (int mi = 0; mi < 2; mi++)
                    wmma::mma_sync(acc[mi][ni], a[mi], b[ni], acc[mi][ni]);
            }
        }
        #pragma unroll
        for (int mi = 0; mi < 2; mi++)
            #pragma unroll
            for (int ni = 0; ni < 4; ni++)
                wmma::store_matrix_sync(sS + h * NPAD * LS + (mo + mi * 16) * LS + ni * 16,
                                        acc[mi][ni], LS, wmma::mem_row_major);
    }
    __syncthreads();

    // -------- scale + rel-pos bias + shift mask + softmax (fp32, 1 thread/row) ----
    if (tid < HEADS * NTOK) {
        const int hh = tid / NTOK, i = tid % NTOK;
        float* row = sS + hh * NPAD * LS + i * LS;
        const float* mrow = mask + (long)(w & (NWIN - 1)) * NTOK * NTOK + i * NTOK;
        const int* rrow = relidx + i * NTOK;
        const float scale = 0.17677669529663687f;  // 32^-0.5
        float mx = -1e30f;
        for (int j = 0; j < NTOK; j++) {
            float s = row[j] * scale + __ldg(&rpb[rrow[j] * HEADS + hh]) + mrow[j];
            row[j] = s;
            mx = fmaxf(mx, s);
        }
        float sum = 0.f;
        for (int j = 0; j < NTOK; j++) { float e = __expf(row[j] - mx); row[j] = e; sum += e; }
        float inv = 1.f / sum;
        for (int j = 0; j < NTOK; j++) row[j] *= inv;
        for (int j = NTOK; j < NPAD; j++) row[j] = 0.f;   // kill padded K columns for AV
    }
    __syncthreads();

    // -------- ctx = S @ V (per head, 64x32, k=64) --------
    {
        wmma::fragment<wmma::accumulator, 16, 16, 8, float> acc[2][2];
        #pragma unroll
        for (int mi = 0; mi < 2; mi++)
            #pragma unroll
            for (int ni = 0; ni < 2; ni++) wmma::fill_fragment(acc[mi][ni], 0.f);

        #pragma unroll
        for (int kk = 0; kk < NPAD; kk += 8) {
            wmma::fragment<wmma::matrix_a, 16, 16, 8, wmma::precision::tf32, wmma::row_major> a[2];
            wmma::fragment<wmma::matrix_b, 16, 16, 8, wmma::precision::tf32, wmma::row_major> b[2];
            #pragma unroll
            for (int mi = 0; mi < 2; mi++) {
                wmma::load_matrix_sync(a[mi], sS + h * NPAD * LS + (mo + mi * 16) * LS + kk, LS);
                #pragma unroll
                for (int t = 0; t < a[mi].num_elements; t++)
                    a[mi].x[t] = wmma::__float_to_tf32(a[mi].x[t]);
            }
            #pragma unroll
            for (int ni = 0; ni < 2; ni++) {
                // B(k=j, n) at sV[j*LD + h*HD + n]
                wmma::load_matrix_sync(b[ni], sV + kk * LD + h * HD + ni * 16, LD);
                #pragma unroll
                for (int t = 0; t < b[ni].num_elements; t++)
                    b[ni].x[t] = wmma::__float_to_tf32(b[ni].x[t]);
                #pragma unroll
                for (int mi = 0; mi < 2; mi++)
                    wmma::mma_sync(acc[mi][ni], a[mi], b[ni], acc[mi][ni]);
            }
        }
        #pragma unroll
        for (int mi = 0; mi < 2; mi++)
            #pragma unroll
            for (int ni = 0; ni < 2; ni++)
                wmma::store_matrix_sync(sO + (mo + mi * 16) * LD + h * HD + ni * 16,
                                        acc[mi][ni], LD, wmma::mem_row_major);
    }
    __syncthreads();

    for (int idx = tid; idx < NTOK * CDIM; idx += 256)
        g_ctx[base + idx] = sO[(idx >> 7) * LD + (idx & 127)];
}

// ============================================================================
// launch
// ============================================================================
extern "C" void kernel_launch(void* const* d_in, const int* in_sizes, int n_in,
                              void* d_out, int out_size) {
    const float* q    = (const float*)d_in[0];
    const float* k    = (const float*)d_in[1];
    const float* v    = (const float*)d_in[2];
    const float* mask = (const float*)d_in[3];
    const float* Wq   = (const float*)d_in[4];
    const float* bq   = (const float*)d_in[5];
    const float* Wk   = (const float*)d_in[6];
    const float* bk   = (const float*)d_in[7];
    const float* Wv   = (const float*)d_in[8];
    const float* bv   = (const float*)d_in[9];
    const float* Wo   = (const float*)d_in[10];
    const float* bo   = (const float*)d_in[11];
    const float* rpb  = (const float*)d_in[12];
    const int*   ridx = (const int*)d_in[13];
    float* out = (float*)d_out;

    float *gq, *gk, *gv, *gc;
    cudaGetSymbolAddress((void**)&gq, g_q);
    cudaGetSymbolAddress((void**)&gk, g_k);
    cudaGetSymbolAddress((void**)&gv, g_v);
    cudaGetSymbolAddress((void**)&gc, g_ctx);

    const size_t smemP = (size_t)(2 * 128 * 132) * sizeof(float);                       // 132 KB
    const size_t smemA = (size_t)(4 * 64 * 132 + HEADS * 64 * 68) * sizeof(float);      // 200 KB
    cudaFuncSetAttribute(proj_kernel, cudaFuncAttributeMaxDynamicSharedMemorySize, (int)smemP);
    cudaFuncSetAttribute(attn_kernel, cudaFuncAttributeMaxDynamicSharedMemorySize, (int)smemA);

    const int gridP = BN / 128;  // 1568

    proj_kernel<<<gridP, 256, smemP>>>(q, Wq, bq, gq);
    proj_kernel<<<gridP, 256, smemP>>>(k, Wk, bk, gk);
    proj_kernel<<<gridP, 256, smemP>>>(v, Wv, bv, gv);
    attn_kernel<<<BN / NTOK, 256, smemA>>>(mask, rpb, ridx);
    proj_kernel<<<gridP, 256, smemP>>>(gc, Wo, bo, out);
}

// round 2
// speedup vs baseline: 1.1946x; 1.1946x over previous
#include <cuda_runtime.h>
#include <cuda_bf16.h>
#include <mma.h>

using namespace nvcuda;

#define CDIM   128
#define HEADS  4
#define HD     32
#define NTOK   49
#define NPAD   64
#define NWIN   64
#define NBLK   4096

constexpr int LDX  = 132;   // row stride for 128-wide tiles (floats)
constexpr int LDSS = 68;    // row stride for 64-wide score tiles (floats)

// ---- shared memory layout (floats) ----
constexpr int OFF_X = 0;                       // 64 x 132   = 8448
constexpr int OFF_W = 8448;                    // 128 x 132  = 16896
constexpr int OFF_Q = 25344;                   // 64 x 132
constexpr int OFF_K = 33792;                   // 64 x 132
constexpr int OFF_V = 42240;                   // 64 x 132
constexpr int SMEM_FLOATS = 50688;             // 202,752 bytes
// reused regions:
constexpr int OFF_S = 0;                       // 4 * 64 * 68 = 17408  (over X+W)
constexpr int OFF_O = OFF_Q;                   // ctx over Q
constexpr int OFF_Y = OFF_V;                   // final tile over V

template <class Frag>
__device__ __forceinline__ void to_tf32(Frag& f) {
    #pragma unroll
    for (int t = 0; t < f.num_elements; t++) f.x[t] = wmma::__float_to_tf32(f.x[t]);
}

// load a 49x128 window (contiguous) into 64x132 smem tile, zero-padding rows 49..63
__device__ __forceinline__ void load_x(const float* __restrict__ src, float* sX, int tid) {
    #pragma unroll 4
    for (int i = tid; i < (NPAD * CDIM) / 4; i += 256) {
        int r = (i * 4) >> 7, c = (i * 4) & 127;
        float4 val = (r < NTOK) ? reinterpret_cast<const float4*>(src)[i]
                                : make_float4(0.f, 0.f, 0.f, 0.f);
        *reinterpret_cast<float4*>(&sX[r * LDX + c]) = val;
    }
}

// load 128x128 weight into 128x132 smem tile
__device__ __forceinline__ void load_w(const float* __restrict__ W, float* sW, int tid) {
    #pragma unroll 4
    for (int i = tid; i < (CDIM * CDIM) / 4; i += 256) {
        int r = (i * 4) >> 7, c = (i * 4) & 127;
        *reinterpret_cast<float4*>(&sW[r * LDX + c]) = reinterpret_cast<const float4*>(W)[i];
    }
}

// C[64,128] = A[64,128] @ B^T  (B row-major [j][c] viewed col-major), all ld = LDX
__device__ __forceinline__ void gemm_proj(const float* sA, const float* sB, float* sC, int warp) {
    const int wm = (warp & 1) * 32;
    const int wn = (warp >> 1) * 32;

    wmma::fragment<wmma::accumulator, 16, 16, 8, float> acc[2][2];
    #pragma unroll
    for (int mi = 0; mi < 2; mi++)
        #pragma unroll
        for (int ni = 0; ni < 2; ni++) wmma::fill_fragment(acc[mi][ni], 0.f);

    #pragma unroll 4
    for (int kk = 0; kk < CDIM; kk += 8) {
        wmma::fragment<wmma::matrix_a, 16, 16, 8, wmma::precision::tf32, wmma::row_major> a[2];
        wmma::fragment<wmma::matrix_b, 16, 16, 8, wmma::precision::tf32, wmma::col_major> b[2];
        #pragma unroll
        for (int mi = 0; mi < 2; mi++) {
            wmma::load_matrix_sync(a[mi], sA + (wm + mi * 16) * LDX + kk, LDX);
            to_tf32(a[mi]);
        }
        #pragma unroll
        for (int ni = 0; ni < 2; ni++) {
            wmma::load_matrix_sync(b[ni], sB + (wn + ni * 16) * LDX + kk, LDX);
            to_tf32(b[ni]);
            #pragma unroll
            for (int mi = 0; mi < 2; mi++)
                wmma::mma_sync(acc[mi][ni], a[mi], b[ni], acc[mi][ni]);
        }
    }
    #pragma unroll
    for (int mi = 0; mi < 2; mi++)
        #pragma unroll
        for (int ni = 0; ni < 2; ni++)
            wmma::store_matrix_sync(sC + (wm + mi * 16) * LDX + wn + ni * 16,
                                    acc[mi][ni], LDX, wmma::mem_row_major);
}

__device__ __forceinline__ void bias_pass(float* sC, const float* __restrict__ bias, int tid) {
    #pragma unroll 4
    for (int i = tid; i < (NPAD * CDIM) / 4; i += 256) {
        int r = (i * 4) >> 7, c = (i * 4) & 127;
        float4 v = *reinterpret_cast<float4*>(&sC[r * LDX + c]);
        float4 b = *reinterpret_cast<const float4*>(&bias[c]);
        v.x += b.x; v.y += b.y; v.z += b.z; v.w += b.w;
        *reinterpret_cast<float4*>(&sC[r * LDX + c]) = v;
    }
}

__global__ void __launch_bounds__(256, 1)
fused_wmca_kernel(const float* __restrict__ q_in, const float* __restrict__ k_in,
                  const float* __restrict__ v_in, const float* __restrict__ mask,
                  const float* __restrict__ Wq, const float* __restrict__ bq,
                  const float* __restrict__ Wk, const float* __restrict__ bk,
                  const float* __restrict__ Wv, const float* __restrict__ bv,
                  const float* __restrict__ Wo, const float* __restrict__ bo,
                  const float* __restrict__ rpb, const int* __restrict__ relidx,
                  float* __restrict__ out) {
    extern __shared__ float sm[];
    const int tid = threadIdx.x;
    const int warp = tid >> 5;
    const int w = blockIdx.x;
    const long base = (long)w * NTOK * CDIM;

    // ---------------- Q projection ----------------
    load_x(q_in + base, sm + OFF_X, tid);
    load_w(Wq, sm + OFF_W, tid);
    __syncthreads();
    gemm_proj(sm + OFF_X, sm + OFF_W, sm + OFF_Q, warp);
    __syncthreads();
    bias_pass(sm + OFF_Q, bq, tid);

    // ---------------- K projection ----------------
    load_x(k_in + base, sm + OFF_X, tid);
    load_w(Wk, sm + OFF_W, tid);
    __syncthreads();
    gemm_proj(sm + OFF_X, sm + OFF_W, sm + OFF_K, warp);
    __syncthreads();
    bias_pass(sm + OFF_K, bk, tid);

    // ---------------- V projection ----------------
    load_x(v_in + base, sm + OFF_X, tid);
    load_w(Wv, sm + OFF_W, tid);
    __syncthreads();
    gemm_proj(sm + OFF_X, sm + OFF_W, sm + OFF_V, warp);
    __syncthreads();
    bias_pass(sm + OFF_V, bv, tid);
    // (no sync needed: QK below touches Q/K/S only; X/W reads were synced above)

    // ---------------- S = Q @ K^T per head (writes over X+W region) ----------------
    {
        const int h  = warp >> 1;
        const int mo = (warp & 1) * 32;
        wmma::fragment<wmma::accumulator, 16, 16, 8, float> acc[2][4];
        #pragma unroll
        for (int mi = 0; mi < 2; mi++)
            #pragma unroll
            for (int ni = 0; ni < 4; ni++) wmma::fill_fragment(acc[mi][ni], 0.f);

        #pragma unroll
        for (int kk = 0; kk < HD; kk += 8) {
            wmma::fragment<wmma::matrix_a, 16, 16, 8, wmma::precision::tf32, wmma::row_major> a[2];
            wmma::fragment<wmma::matrix_b, 16, 16, 8, wmma::precision::tf32, wmma::col_major> b[4];
            #pragma unroll
            for (int mi = 0; mi < 2; mi++) {
                wmma::load_matrix_sync(a[mi], sm + OFF_Q + (mo + mi * 16) * LDX + h * HD + kk, LDX);
                to_tf32(a[mi]);
            }
            #pragma unroll
            for (int ni = 0; ni < 4; ni++) {
                wmma::load_matrix_sync(b[ni], sm + OFF_K + (ni * 16) * LDX + h * HD + kk, LDX);
                to_tf32(b[ni]);
                #pragma unroll
                for (int mi = 0; mi < 2; mi++)
                    wmma::mma_sync(acc[mi][ni], a[mi], b[ni], acc[mi][ni]);
            }
        }
        #pragma unroll
        for (int mi = 0; mi < 2; mi++)
            #pragma unroll
            for (int ni = 0; ni < 4; ni++)
                wmma::store_matrix_sync(sm + OFF_S + h * NPAD * LDSS + (mo + mi * 16) * LDSS + ni * 16,
                                        acc[mi][ni], LDSS, wmma::mem_row_major);
    }
    __syncthreads();

    // ---------------- scale + rpb bias + shift mask + softmax ----------------
    if (tid < HEADS * NTOK) {
        const int hh = tid / NTOK, i = tid % NTOK;
        float* row = sm + OFF_S + hh * NPAD * LDSS + i * LDSS;
        const float* mrow = mask + (long)(w & (NWIN - 1)) * NTOK * NTOK + i * NTOK;
        const int* rrow = relidx + i * NTOK;
        const float scale = 0.17677669529663687f;  // 32^-0.5
        float mx = -1e30f;
        #pragma unroll 7
        for (int j = 0; j < NTOK; j++) {
            float s = row[j] * scale + __ldg(&rpb[rrow[j] * HEADS + hh]) + mrow[j];
            row[j] = s;
            mx = fmaxf(mx, s);
        }
        float sum = 0.f;
        #pragma unroll 7
        for (int j = 0; j < NTOK; j++) { float e = __expf(row[j] - mx); row[j] = e; sum += e; }
        float inv = 1.f / sum;
        #pragma unroll 7
        for (int j = 0; j < NTOK; j++) row[j] *= inv;
        #pragma unroll
        for (int j = NTOK; j < NPAD; j++) row[j] = 0.f;   // kill padded K columns
    }
    __syncthreads();

    // ---------------- ctx = S @ V per head (ctx over Q region) ----------------
    {
        const int h  = warp >> 1;
        const int mo = (warp & 1) * 32;
        wmma::fragment<wmma::accumulator, 16, 16, 8, float> acc[2][2];
        #pragma unroll
        for (int mi = 0; mi < 2; mi++)
            #pragma unroll
            for (int ni = 0; ni < 2; ni++) wmma::fill_fragment(acc[mi][ni], 0.f);

        #pragma unroll 4
        for (int kk = 0; kk < NPAD; kk += 8) {
            wmma::fragment<wmma::matrix_a, 16, 16, 8, wmma::precision::tf32, wmma::row_major> a[2];
            wmma::fragment<wmma::matrix_b, 16, 16, 8, wmma::precision::tf32, wmma::row_major> b[2];
            #pragma unroll
            for (int mi = 0; mi < 2; mi++) {
                wmma::load_matrix_sync(a[mi], sm + OFF_S + h * NPAD * LDSS + (mo + mi * 16) * LDSS + kk, LDSS);
                to_tf32(a[mi]);
            }
            #pragma unroll
            for (int ni = 0; ni < 2; ni++) {
                wmma::load_matrix_sync(b[ni], sm + OFF_V + kk * LDX + h * HD + ni * 16, LDX);
                to_tf32(b[ni]);
                #pragma unroll
                for (int mi = 0; mi < 2; mi++)
                    wmma::mma_sync(acc[mi][ni], a[mi], b[ni], acc[mi][ni]);
            }
        }
        #pragma unroll
        for (int mi = 0; mi < 2; mi++)
            #pragma unroll
            for (int ni = 0; ni < 2; ni++)
                wmma::store_matrix_sync(sm + OFF_O + (mo + mi * 16) * LDX + h * HD + ni * 16,
                                        acc[mi][ni], LDX, wmma::mem_row_major);
    }
    __syncthreads();

    // ---------------- output projection: Y = ctx @ Wo^T + bo ----------------
    load_w(Wo, sm + OFF_W, tid);   // over dead S region
    __syncthreads();
    gemm_proj(sm + OFF_O, sm + OFF_W, sm + OFF_Y, warp);
    __syncthreads();

    #pragma unroll 4
    for (int i = tid; i < (NTOK * CDIM) / 4; i += 256) {
        int r = (i * 4) >> 7, c = (i * 4) & 127;
        float4 v = *reinterpret_cast<float4*>(&sm[OFF_Y + r * LDX + c]);
        float4 b = *reinterpret_cast<const float4*>(&bo[c]);
        v.x += b.x; v.y += b.y; v.z += b.z; v.w += b.w;
        reinterpret_cast<float4*>(out + base)[i] = v;
    }
}

// ============================================================================
// launch
// ============================================================================
extern "C" void kernel_launch(void* const* d_in, const int* in_sizes, int n_in,
                              void* d_out, int out_size) {
    const float* q    = (const float*)d_in[0];
    const float* k    = (const float*)d_in[1];
    const float* v    = (const float*)d_in[2];
    const float* mask = (const float*)d_in[3];
    const float* Wq   = (const float*)d_in[4];
    const float* bq   = (const float*)d_in[5];
    const float* Wk   = (const float*)d_in[6];
    const float* bk   = (const float*)d_in[7];
    const float* Wv   = (const float*)d_in[8];
    const float* bv   = (const float*)d_in[9];
    const float* Wo   = (const float*)d_in[10];
    const float* bo   = (const float*)d_in[11];
    const float* rpb  = (const float*)d_in[12];
    const int*   ridx = (const int*)d_in[13];
    float* out = (float*)d_out;

    const size_t smem = (size_t)SMEM_FLOATS * sizeof(float);   // 202,752 B
    cudaFuncSetAttribute(fused_wmca_kernel, cudaFuncAttributeMaxDynamicSharedMemorySize, (int)smem);

    fused_wmca_kernel<<<NBLK, 256, smem>>>(q, k, v, mask, Wq, bq, Wk, bk, Wv, bv,
                                           Wo, bo, rpb, ridx, out);
}